// round 14
// baseline (speedup 1.0000x reference)
#include <cuda_runtime.h>
#include <math.h>

#define Bz 32
#define Tz 512
#define Jz 128
#define Dz 256
#define Gz 768   // 3*D

// ------------------------- device scratch (no allocs allowed) -------------------------
__device__ float g_gi[4][Tz*Bz*Gz];      // long instances, scan order [s][b][g]
__device__ float g_gic[2][Jz*Bz*Gz];     // cmnt instances
__device__ float g_ctx[2][Bz*Tz*2*Dz];   // bigru out, w2-scaled: [b][t][2D]
__device__ float g_cm[Bz*Jz*2*Dz];       // cmnt bigru out, raw
__device__ float g_S[2][Bz*Tz*Jz];       // similarity scores
__device__ float g_Sd[Bz*2*Jz];          // S_diff

__device__ __forceinline__ float fsig(float x) { return 1.f/(1.f + __expf(-x)); }
__device__ __forceinline__ float ftanh(float x) { return 1.f - 2.f/(1.f + __expf(2.f*x)); }

// packed fp32 helpers (FFMA2 path — only reachable via PTX fma.rn.f32x2)
__device__ __forceinline__ void ffma2(unsigned long long& a, unsigned long long x,
                                      unsigned long long w) {
    asm("fma.rn.f32x2 %0, %1, %2, %0;" : "+l"(a) : "l"(x), "l"(w));
}
__device__ __forceinline__ unsigned long long dup2(float v) {
    unsigned long long d; unsigned r = __float_as_uint(v);
    asm("mov.b64 %0, {%1, %1};" : "=l"(d) : "r"(r));
    return d;
}
__device__ __forceinline__ float2 unpk(unsigned long long a) {
    unsigned lo, hi;
    asm("mov.b64 {%0, %1}, %2;" : "=r"(lo), "=r"(hi) : "l"(a));
    return make_float2(__uint_as_float(lo), __uint_as_float(hi));
}

__device__ __forceinline__ unsigned smem_u32(const void* p) {
    unsigned a;
    asm("{ .reg .u64 t; cvta.to.shared.u64 t, %1; cvt.u32.u64 %0, t; }" : "=r"(a) : "l"(p));
    return a;
}
__device__ __forceinline__ unsigned cta_rank() {
    unsigned r; asm("mov.u32 %0, %%cluster_ctarank;" : "=r"(r)); return r;
}
__device__ __forceinline__ void st_dsmem(unsigned addr, unsigned rank, float v) {
    unsigned ra;
    asm volatile("mapa.shared::cluster.u32 %0, %1, %2;" : "=r"(ra) : "r"(addr), "r"(rank));
    asm volatile("st.shared::cluster.f32 [%0], %1;" :: "r"(ra), "f"(v) : "memory");
}
#define CLUSTER_ARRIVE() asm volatile("barrier.cluster.arrive.aligned;" ::: "memory")
#define CLUSTER_WAIT()   asm volatile("barrier.cluster.wait.aligned;"   ::: "memory")

// ------------- gi = emb[token] @ wih^T + bih (gather-fused tiled SGEMM, FFMA2) -------------
__global__ __launch_bounds__(256) void k_gi(
    const int* __restrict__ cm_tok, const int* __restrict__ src_tok,
    const int* __restrict__ tgt_tok, const float* __restrict__ emb,
    const float* __restrict__ wihf, const float* __restrict__ bihf,
    const float* __restrict__ wihb, const float* __restrict__ bihb)
{
    const int inst = blockIdx.z;
    const int dir  = inst & 1;
    const int seq  = inst >> 1;                 // 0 src, 1 tgt, 2 cmnt
    const int Tlen = (seq == 2) ? Jz : Tz;
    const int rows = Tlen * Bz;
    const int rb = blockIdx.x * 128;
    if (rb >= rows) return;
    const int gb = blockIdx.y * 64;

    const int* tok = (seq == 0) ? src_tok : (seq == 1) ? tgt_tok : cm_tok;
    const float* W    = dir ? wihb : wihf;
    const float* bias = dir ? bihb : bihf;
    float* C = (inst < 4) ? &g_gi[inst][0] : &g_gic[inst-4][0];

    __shared__ float As[16][132];
    __shared__ float Bs[16][68];
    const int tid = threadIdx.x;
    const int tx = tid & 15, ty = tid >> 4;
    const int lrA = tid >> 1, lkA = (tid & 1) * 8;
    const int lrB = tid >> 2, lkB = (tid & 3) * 4;

    int rg = rb + lrA;
    int s  = rg >> 5, bb = rg & 31;
    int ts = dir ? (Tlen - 1 - s) : s;
    const float* Arow = emb + (size_t)tok[bb*Tlen + ts] * Dz;
    const float* Brow = W   + (size_t)(gb + lrB) * Dz;

    unsigned long long acc[4][4];   // [rowpair][j]
#pragma unroll
    for (int p = 0; p < 4; p++)
#pragma unroll
        for (int j = 0; j < 4; j++) acc[p][j] = 0ull;

    for (int k0 = 0; k0 < Dz; k0 += 16) {
        float4 a0 = *(const float4*)(Arow + k0 + lkA);
        float4 a1 = *(const float4*)(Arow + k0 + lkA + 4);
        float4 bv = *(const float4*)(Brow + k0 + lkB);
        As[lkA+0][lrA]=a0.x; As[lkA+1][lrA]=a0.y; As[lkA+2][lrA]=a0.z; As[lkA+3][lrA]=a0.w;
        As[lkA+4][lrA]=a1.x; As[lkA+5][lrA]=a1.y; As[lkA+6][lrA]=a1.z; As[lkA+7][lrA]=a1.w;
        Bs[lkB+0][lrB]=bv.x; Bs[lkB+1][lrB]=bv.y; Bs[lkB+2][lrB]=bv.z; Bs[lkB+3][lrB]=bv.w;
        __syncthreads();
#pragma unroll
        for (int kk = 0; kk < 16; kk++) {
            ulonglong2 a01 = *(const ulonglong2*)&As[kk][ty*8];
            ulonglong2 a23 = *(const ulonglong2*)&As[kk][ty*8+4];
            float4 rb4 = *(const float4*)&Bs[kk][tx*4];
            unsigned long long bd[4] = { dup2(rb4.x), dup2(rb4.y), dup2(rb4.z), dup2(rb4.w) };
            unsigned long long ap[4] = { a01.x, a01.y, a23.x, a23.y };
#pragma unroll
            for (int p = 0; p < 4; p++)
#pragma unroll
                for (int j = 0; j < 4; j++) ffma2(acc[p][j], ap[p], bd[j]);
        }
        __syncthreads();
    }
    float4 b4 = *(const float4*)(bias + gb + tx*4);
    float bb4[4] = { b4.x, b4.y, b4.z, b4.w };
#pragma unroll
    for (int p = 0; p < 4; p++) {
        int r0 = rb + ty*8 + 2*p;
        float v0[4], v1[4];
#pragma unroll
        for (int j = 0; j < 4; j++) {
            float2 u = unpk(acc[p][j]);
            v0[j] = u.x + bb4[j];
            v1[j] = u.y + bb4[j];
        }
        *(float4*)&C[(size_t)r0*Gz + gb + tx*4]     = *(float4*)v0;
        *(float4*)&C[(size_t)(r0+1)*Gz + gb + tx*4] = *(float4*)v1;
    }
}

// ------------------- clustered GRU scan (single wave, all 6 instances) -------------------
// 24 clusters x 4 CTAs = 96 CTAs, everything resident in wave 1 (cmnt rides free).
// Cluster = (instance, 8 batch rows). whh sharded by h-column (rank owns 64 cols ->
// 192 gate-rows). 256 thr; per-thread 8 rows x 1 col x K/4, FFMA2 over K pairs.
// kq INTERLEAVED at 16B granularity (lane kq reads chunks q*16 + kq*4 floats):
// H loads broadcast (1 wf), W loads at the 512B bandwidth floor (4 wf).
// Butterfly shfl leaves full sums in all lanes; lane kq owns rows r0+2kq, r0+2kq+1.
// Split cluster barrier hides gi prefetch + peer skew.
// smem: Ws[192][260] + Hs[2][8][260] = 216320 B dynamic.
__global__ __launch_bounds__(256) __cluster_dims__(4, 1, 1) void k_scan_cl(
    const float* __restrict__ whhf, const float* __restrict__ whhb,
    const float* __restrict__ bhhf, const float* __restrict__ bhhb,
    const float* __restrict__ w2)
{
    extern __shared__ float sm[];
    float* Ws  = sm;                  // [(g*64+cc)*260 + k]
    float* Hs0 = sm + 192*260;        // [8][260]
    float* Hs1 = Hs0 + 8*260;

    const unsigned rank = cta_rank();
    const int cl = blockIdx.x >> 2;
    int inst, r0, Tlen;
    const float* gi_base; float* out_base;
    if (cl < 16) {                      // long: 4 inst x 2 rowgroups... (4 inst x 4 groups)
        inst = cl >> 2; r0 = (cl & 3) * 8; Tlen = Tz;
        gi_base = &g_gi[inst][0]; out_base = &g_ctx[inst>>1][0];
    } else {                            // cmnt: 2 inst x 4 rowgroups
        int q = cl - 16;
        inst = 4 + (q >> 2); r0 = (q & 3) * 8; Tlen = Jz;
        gi_base = &g_gic[inst-4][0]; out_base = &g_cm[0];
    }
    const int c0  = rank * 64;
    const int dir = inst & 1;
    const float* whh = dir ? whhb : whhf;
    const float* bhh = dir ? bhhb : bhhf;

    const int tid  = threadIdx.x;
    const int w    = tid >> 5;
    const int lane = tid & 31;
    const int kq   = lane >> 3;          // K quarter (shfl-reducible: xor 8,16)
    const int cs   = lane & 7;
    const int c    = c0 + w*8 + cs;      // global h-col 0..255
    const int koff = kq * 4;             // 16B-interleaved k offset (floats)
    const int re   = r0 + 2*kq;          // epilogue rows re, re+1 (local 2kq, 2kq+1)

    // load whh shard: 192 rows (3 gates x 64 cols) x 256
    for (int q = tid; q < 192*64; q += 256) {
        int row = q >> 6, kk = (q & 63) * 4;
        int g = row >> 6, cc = row & 63;
        *(float4*)&Ws[row*260 + kk] =
            *(const float4*)(whh + (size_t)(g*256 + c0 + cc)*Dz + kk);
    }
    // zero both H buffers (h0 = 0)
    for (int q = tid; q < 2*8*260; q += 256) Hs0[q] = 0.f;

    const float bR = bhh[c], bZ = bhh[256+c], bN = bhh[512+c];
    const float w2c = (inst < 4) ? w2[dir*256 + c] : 1.0f;
    const int cw = w*8 + cs;
    const float* wr = &Ws[(0*64 + cw)*260 + koff];
    const float* wz = &Ws[(1*64 + cw)*260 + koff];
    const float* wn = &Ws[(2*64 + cw)*260 + koff];
    const unsigned hn_u32[2] = { smem_u32(Hs0), smem_u32(Hs1) };

    __syncthreads();
    CLUSTER_ARRIVE();    // release zeroed buffers

    for (int s = 0; s < Tlen; s++) {
        const float* Hb = (s & 1) ? Hs1 : Hs0;
        const float* Hc = Hb + koff;
        const unsigned HnU = hn_u32[(s & 1) ^ 1];

        // prefetch gi for this lane's two epilogue rows (issued before the barrier wait)
        float gr0, gz0, gn0, gr1, gz1, gn1;
        {
            const float* gp0 = gi_base + (size_t)(s*32 + re)*Gz;
            const float* gp1 = gp0 + Gz;
            gr0 = __ldcs(gp0 + c); gz0 = __ldcs(gp0 + 256 + c); gn0 = __ldcs(gp0 + 512 + c);
            gr1 = __ldcs(gp1 + c); gz1 = __ldcs(gp1 + 256 + c); gn1 = __ldcs(gp1 + 512 + c);
        }
        CLUSTER_WAIT();   // prev-step DSMEM stores now visible

        unsigned long long aR[8], aZ[8], aN[8];
#pragma unroll
        for (int i = 0; i < 8; i++) { aR[i]=0ull; aZ[i]=0ull; aN[i]=0ull; }
#pragma unroll 4
        for (int q = 0; q < 16; q++) {
            const int off = q * 16;      // 16 floats per interleave group
            ulonglong2 vr = *(const ulonglong2*)(wr + off);
            ulonglong2 vz = *(const ulonglong2*)(wz + off);
            ulonglong2 vn = *(const ulonglong2*)(wn + off);
#pragma unroll
            for (int i = 0; i < 8; i++) {
                ulonglong2 x = *(const ulonglong2*)(Hc + i*260 + off);
                ffma2(aR[i], x.x, vr.x); ffma2(aR[i], x.y, vr.y);
                ffma2(aZ[i], x.x, vz.x); ffma2(aZ[i], x.y, vz.y);
                ffma2(aN[i], x.x, vn.x); ffma2(aN[i], x.y, vn.y);
            }
        }
        // horizontal + cross-kq butterfly (full sums in every lane)
        float sR[8], sZ[8], sN[8];
#pragma unroll
        for (int i = 0; i < 8; i++) {
            float2 u;
            u = unpk(aR[i]); sR[i] = u.x + u.y;
            u = unpk(aZ[i]); sZ[i] = u.x + u.y;
            u = unpk(aN[i]); sN[i] = u.x + u.y;
            sR[i] += __shfl_xor_sync(0xFFFFFFFFu, sR[i], 8);
            sR[i] += __shfl_xor_sync(0xFFFFFFFFu, sR[i], 16);
            sZ[i] += __shfl_xor_sync(0xFFFFFFFFu, sZ[i], 8);
            sZ[i] += __shfl_xor_sync(0xFFFFFFFFu, sZ[i], 16);
            sN[i] += __shfl_xor_sync(0xFFFFFFFFu, sN[i], 8);
            sN[i] += __shfl_xor_sync(0xFFFFFFFFu, sN[i], 16);
        }

        // epilogue: lane kq owns local rows 2kq, 2kq+1
        {
            const int tact = dir ? (Tlen - 1 - s) : s;
            const int i0 = 2*kq;
            float g_r[2] = {gr0, gr1}, g_z[2] = {gz0, gz1}, g_n[2] = {gn0, gn1};
#pragma unroll
            for (int q = 0; q < 2; q++) {
                int i = i0 + q;
                float rr2 = fsig(g_r[q] + sR[i] + bR);
                float zz  = fsig(g_z[q] + sZ[i] + bZ);
                float nn  = ftanh(g_n[q] + rr2*(sN[i] + bN));
                float hp  = Hb[i*260 + c];
                float h   = (1.f - zz)*nn + zz*hp;
                out_base[((size_t)(r0+i)*Tlen + tact)*(2*Dz) + dir*256 + c] = h * w2c;
                unsigned a = HnU + (unsigned)(i*260 + c) * 4u;
#pragma unroll
                for (unsigned p = 0; p < 4; p++) st_dsmem(a, p, h);
            }
        }
        CLUSTER_ARRIVE();   // release this step's DSMEM stores
    }
    CLUSTER_WAIT();         // consume final arrive before exit
}

// ------------- S[b,t,j] = sum_d ctxS[b,t,d]*cm[b,j,d] + action*w2[512] (FFMA2) -------------
__global__ __launch_bounds__(256) void k_sim(
    const int* __restrict__ src_act, const int* __restrict__ tgt_act,
    const float* __restrict__ w2)
{
    const int side = blockIdx.z;
    const int b    = blockIdx.y;
    const int tb   = blockIdx.x * 64;
    const float* A = &g_ctx[side][(size_t)b*Tz*2*Dz];   // [t][512]
    const float* Bm= &g_cm[(size_t)b*Jz*2*Dz];          // [j][512]
    const int* act = side ? tgt_act : src_act;
    const float wA = w2[2*Dz];

    __shared__ float As[16][68];
    __shared__ float Bs[16][132];
    const int tid = threadIdx.x;
    const int tx = tid & 15, ty = tid >> 4;
    const int lrA = tid >> 2, lkA = (tid & 3) * 4;
    const int lrB = tid >> 1, lkB = (tid & 1) * 8;

    unsigned long long acc[4][4];   // [i][jpair]
#pragma unroll
    for (int i = 0; i < 4; i++)
#pragma unroll
        for (int q = 0; q < 4; q++) acc[i][q] = 0ull;

    const float* Arow = A + (size_t)(tb + lrA)*(2*Dz);
    const float* Brow = Bm + (size_t)lrB*(2*Dz);

    for (int k0 = 0; k0 < 2*Dz; k0 += 16) {
        float4 a = *(const float4*)(Arow + k0 + lkA);
        As[lkA+0][lrA]=a.x; As[lkA+1][lrA]=a.y; As[lkA+2][lrA]=a.z; As[lkA+3][lrA]=a.w;
        float4 b0 = *(const float4*)(Brow + k0 + lkB);
        float4 b1 = *(const float4*)(Brow + k0 + lkB + 4);
        Bs[lkB+0][lrB]=b0.x; Bs[lkB+1][lrB]=b0.y; Bs[lkB+2][lrB]=b0.z; Bs[lkB+3][lrB]=b0.w;
        Bs[lkB+4][lrB]=b1.x; Bs[lkB+5][lrB]=b1.y; Bs[lkB+6][lrB]=b1.z; Bs[lkB+7][lrB]=b1.w;
        __syncthreads();
#pragma unroll
        for (int kk = 0; kk < 16; kk++) {
            float4 ra = *(const float4*)&As[kk][ty*4];
            unsigned long long ad[4] = { dup2(ra.x), dup2(ra.y), dup2(ra.z), dup2(ra.w) };
            ulonglong2 b01 = *(const ulonglong2*)&Bs[kk][tx*8];
            ulonglong2 b23 = *(const ulonglong2*)&Bs[kk][tx*8+4];
            unsigned long long bp[4] = { b01.x, b01.y, b23.x, b23.y };
#pragma unroll
            for (int i = 0; i < 4; i++)
#pragma unroll
                for (int q = 0; q < 4; q++) ffma2(acc[i][q], ad[i], bp[q]);
        }
        __syncthreads();
    }
#pragma unroll
    for (int i = 0; i < 4; i++) {
        int t = tb + ty*4 + i;
        float aterm = (float)act[b*Tz + t] * wA;
        float* Sp = &g_S[side][((size_t)b*Tz + t)*Jz];
        float v[8];
#pragma unroll
        for (int q = 0; q < 4; q++) {
            float2 u = unpk(acc[i][q]);
            v[2*q] = u.x + aterm; v[2*q+1] = u.y + aterm;
        }
        *(float4*)&Sp[tx*8]   = *(float4*)&v[0];
        *(float4*)&Sp[tx*8+4] = *(float4*)&v[4];
    }
}

// --------- per (side,b): m_t = max_j S; w = softmax_t(m); out_j = sum_t w_t S[t,j] ---------
__global__ __launch_bounds__(256) void k_reduce() {
    const int b = blockIdx.x, side = blockIdx.y;
    const float* S = &g_S[side][(size_t)b*Tz*Jz];
    __shared__ float mrow[512];
    __shared__ float red[256];
    const int tid = threadIdx.x;

    for (int t = tid; t < Tz; t += 256) {
        const float4* row = (const float4*)(S + (size_t)t*Jz);
        float m = -3.4e38f;
#pragma unroll 4
        for (int q = 0; q < 32; q++) {
            float4 v = row[q];
            m = fmaxf(m, fmaxf(fmaxf(v.x, v.y), fmaxf(v.z, v.w)));
        }
        mrow[t] = m;
    }
    __syncthreads();
    red[tid] = fmaxf(mrow[tid], mrow[tid+256]);
    __syncthreads();
    for (int st = 128; st > 0; st >>= 1) {
        if (tid < st) red[tid] = fmaxf(red[tid], red[tid+st]);
        __syncthreads();
    }
    float M = red[0];
    __syncthreads();
    float e1 = __expf(mrow[tid] - M), e2 = __expf(mrow[tid+256] - M);
    mrow[tid] = e1; mrow[tid+256] = e2;
    red[tid] = e1 + e2;
    __syncthreads();
    for (int st = 128; st > 0; st >>= 1) {
        if (tid < st) red[tid] += red[tid+st];
        __syncthreads();
    }
    float inv = 1.f / red[0];
    __syncthreads();
    mrow[tid] *= inv; mrow[tid+256] *= inv;
    __syncthreads();

    const int j = tid & 127, half = tid >> 7;
    float acc = 0.f;
    for (int t = half*256; t < half*256 + 256; t++)
        acc += mrow[t] * S[(size_t)t*Jz + j];
    red[tid] = acc;
    __syncthreads();
    if (tid < 128)
        g_Sd[b*(2*Jz) + side*Jz + j] = red[j] + red[128 + j];
}

// ---------------- result = S_diff @ rank_w + rank_b; emit (result, S_diff) ----------------
__global__ __launch_bounds__(256) void k_final(
    const float* __restrict__ rank_w, const float* __restrict__ rank_b,
    float* __restrict__ out)
{
    const int tid = threadIdx.x;
    for (int i = tid; i < Bz*2*Jz; i += 256) out[32 + i] = g_Sd[i];
    __shared__ float red[256];
    const int b = tid >> 3, l = tid & 7;
    float p = 0.f;
    for (int q = l; q < 2*Jz; q += 8) p += g_Sd[b*(2*Jz) + q] * rank_w[q];
    red[tid] = p;
    __syncthreads();
    if (l == 0) {
        float s = 0.f;
#pragma unroll
        for (int k = 0; k < 8; k++) s += red[b*8 + k];
        out[b] = s + rank_b[0];
    }
}

// ------------------------- launch -------------------------
extern "C" void kernel_launch(void* const* d_in, const int* in_sizes, int n_in,
                              void* d_out, int out_size) {
    const int*   cm_tok = (const int*)  d_in[0];
    const int*   src_t  = (const int*)  d_in[1];
    const int*   tgt_t  = (const int*)  d_in[2];
    const int*   src_a  = (const int*)  d_in[3];
    const int*   tgt_a  = (const int*)  d_in[4];
    const float* emb    = (const float*)d_in[5];
    const float* wihf   = (const float*)d_in[6];
    const float* whhf   = (const float*)d_in[7];
    const float* bihf   = (const float*)d_in[8];
    const float* bhhf   = (const float*)d_in[9];
    const float* wihb   = (const float*)d_in[10];
    const float* whhb   = (const float*)d_in[11];
    const float* bihb   = (const float*)d_in[12];
    const float* bhhb   = (const float*)d_in[13];
    const float* w2     = (const float*)d_in[14];
    const float* rank_w = (const float*)d_in[15];
    const float* rank_b = (const float*)d_in[16];
    float* out = (float*)d_out;

    const int scanSmem = (192*260 + 2*8*260) * sizeof(float);   // 216320 B
    cudaFuncSetAttribute(k_scan_cl, cudaFuncAttributeMaxDynamicSharedMemorySize, scanSmem);

    k_gi<<<dim3(128, 12, 6), 256>>>(cm_tok, src_t, tgt_t, emb, wihf, bihf, wihb, bihb);
    // 24 clusters (16 long + 8 cmnt) x 4 CTAs = 96 CTAs — single wave, cmnt rides free
    k_scan_cl<<<96, 256, scanSmem>>>(whhf, whhb, bhhf, bhhb, w2);
    k_sim<<<dim3(8, 32, 2), 256>>>(src_a, tgt_a, w2);
    k_reduce<<<dim3(32, 2), 256>>>();
    k_final<<<1, 256>>>(rank_w, rank_b, out);
}

// round 17
// speedup vs baseline: 1.4500x; 1.4500x over previous
#include <cuda_runtime.h>
#include <math.h>

#define Bz 32
#define Tz 512
#define Jz 128
#define Dz 256
#define Gz 768   // 3*D

// ------------------------- device scratch (no allocs allowed) -------------------------
__device__ float g_gi[4][Tz*Bz*Gz];      // long instances, scan order [s][b][g]
__device__ float g_gic[2][Jz*Bz*Gz];     // cmnt instances (0=fwd, 1=bwd)
__device__ float g_ctx[2][Bz*Tz*2*Dz];   // bigru out, w2-scaled: [b][t][2D]
__device__ float g_cm[Bz*Jz*2*Dz];       // cmnt bigru out, raw
__device__ float g_S[2][Bz*Tz*Jz];       // similarity scores
__device__ float g_Sd[Bz*2*Jz];          // S_diff

__device__ __forceinline__ float fsig(float x) { return 1.f/(1.f + __expf(-x)); }
__device__ __forceinline__ float ftanh(float x) { return 1.f - 2.f/(1.f + __expf(2.f*x)); }

// packed fp32 helpers (FFMA2 path — only reachable via PTX fma.rn.f32x2)
__device__ __forceinline__ void ffma2(unsigned long long& a, unsigned long long x,
                                      unsigned long long w) {
    asm("fma.rn.f32x2 %0, %1, %2, %0;" : "+l"(a) : "l"(x), "l"(w));
}
__device__ __forceinline__ unsigned long long dup2(float v) {
    unsigned long long d; unsigned r = __float_as_uint(v);
    asm("mov.b64 %0, {%1, %1};" : "=l"(d) : "r"(r));
    return d;
}
__device__ __forceinline__ float2 unpk(unsigned long long a) {
    unsigned lo, hi;
    asm("mov.b64 {%0, %1}, %2;" : "=r"(lo), "=r"(hi) : "l"(a));
    return make_float2(__uint_as_float(lo), __uint_as_float(hi));
}

__device__ __forceinline__ unsigned smem_u32(const void* p) {
    unsigned a;
    asm("{ .reg .u64 t; cvta.to.shared.u64 t, %1; cvt.u32.u64 %0, t; }" : "=r"(a) : "l"(p));
    return a;
}
__device__ __forceinline__ unsigned cta_rank() {
    unsigned r; asm("mov.u32 %0, %%cluster_ctarank;" : "=r"(r)); return r;
}
__device__ __forceinline__ void st_dsmem(unsigned addr, unsigned rank, float v) {
    unsigned ra;
    asm volatile("mapa.shared::cluster.u32 %0, %1, %2;" : "=r"(ra) : "r"(addr), "r"(rank));
    asm volatile("st.shared::cluster.f32 [%0], %1;" :: "r"(ra), "f"(v) : "memory");
}
#define CLUSTER_ARRIVE() asm volatile("barrier.cluster.arrive.aligned;" ::: "memory")
#define CLUSTER_WAIT()   asm volatile("barrier.cluster.wait.aligned;"   ::: "memory")

// ------------- gi = emb[token] @ wih^T + bih (gather-fused tiled SGEMM, FFMA2) -------------
__global__ __launch_bounds__(256) void k_gi(
    const int* __restrict__ cm_tok, const int* __restrict__ src_tok,
    const int* __restrict__ tgt_tok, const float* __restrict__ emb,
    const float* __restrict__ wihf, const float* __restrict__ bihf,
    const float* __restrict__ wihb, const float* __restrict__ bihb)
{
    const int inst = blockIdx.z;
    const int dir  = inst & 1;
    const int seq  = inst >> 1;                 // 0 src, 1 tgt, 2 cmnt
    const int Tlen = (seq == 2) ? Jz : Tz;
    const int rows = Tlen * Bz;
    const int rb = blockIdx.x * 128;
    if (rb >= rows) return;
    const int gb = blockIdx.y * 64;

    const int* tok = (seq == 0) ? src_tok : (seq == 1) ? tgt_tok : cm_tok;
    const float* W    = dir ? wihb : wihf;
    const float* bias = dir ? bihb : bihf;
    float* C = (inst < 4) ? &g_gi[inst][0] : &g_gic[dir][0];

    __shared__ float As[16][132];
    __shared__ float Bs[16][68];
    const int tid = threadIdx.x;
    const int tx = tid & 15, ty = tid >> 4;
    const int lrA = tid >> 1, lkA = (tid & 1) * 8;
    const int lrB = tid >> 2, lkB = (tid & 3) * 4;

    int rg = rb + lrA;
    int s  = rg >> 5, bb = rg & 31;
    int ts = dir ? (Tlen - 1 - s) : s;
    const float* Arow = emb + (size_t)tok[bb*Tlen + ts] * Dz;
    const float* Brow = W   + (size_t)(gb + lrB) * Dz;

    unsigned long long acc[4][4];   // [rowpair][j]
#pragma unroll
    for (int p = 0; p < 4; p++)
#pragma unroll
        for (int j = 0; j < 4; j++) acc[p][j] = 0ull;

    for (int k0 = 0; k0 < Dz; k0 += 16) {
        float4 a0 = *(const float4*)(Arow + k0 + lkA);
        float4 a1 = *(const float4*)(Arow + k0 + lkA + 4);
        float4 bv = *(const float4*)(Brow + k0 + lkB);
        As[lkA+0][lrA]=a0.x; As[lkA+1][lrA]=a0.y; As[lkA+2][lrA]=a0.z; As[lkA+3][lrA]=a0.w;
        As[lkA+4][lrA]=a1.x; As[lkA+5][lrA]=a1.y; As[lkA+6][lrA]=a1.z; As[lkA+7][lrA]=a1.w;
        Bs[lkB+0][lrB]=bv.x; Bs[lkB+1][lrB]=bv.y; Bs[lkB+2][lrB]=bv.z; Bs[lkB+3][lrB]=bv.w;
        __syncthreads();
#pragma unroll
        for (int kk = 0; kk < 16; kk++) {
            ulonglong2 a01 = *(const ulonglong2*)&As[kk][ty*8];
            ulonglong2 a23 = *(const ulonglong2*)&As[kk][ty*8+4];
            float4 rb4 = *(const float4*)&Bs[kk][tx*4];
            unsigned long long bd[4] = { dup2(rb4.x), dup2(rb4.y), dup2(rb4.z), dup2(rb4.w) };
            unsigned long long ap[4] = { a01.x, a01.y, a23.x, a23.y };
#pragma unroll
            for (int p = 0; p < 4; p++)
#pragma unroll
                for (int j = 0; j < 4; j++) ffma2(acc[p][j], ap[p], bd[j]);
        }
        __syncthreads();
    }
    float4 b4 = *(const float4*)(bias + gb + tx*4);
    float bb4[4] = { b4.x, b4.y, b4.z, b4.w };
#pragma unroll
    for (int p = 0; p < 4; p++) {
        int r0 = rb + ty*8 + 2*p;
        float v0[4], v1[4];
#pragma unroll
        for (int j = 0; j < 4; j++) {
            float2 u = unpk(acc[p][j]);
            v0[j] = u.x + bb4[j];
            v1[j] = u.y + bb4[j];
        }
        *(float4*)&C[(size_t)r0*Gz + gb + tx*4]     = *(float4*)v0;
        *(float4*)&C[(size_t)(r0+1)*Gz + gb + tx*4] = *(float4*)v1;
    }
}

// ------------------------- clustered GRU scan (cmnt carried) -------------------------
// 32 clusters x 4 CTAs = 128 CTAs, single wave. Cluster = (long instance, 4 batch rows)
// PLUS 2 carried cmnt rows of the same direction (weights are SHARED between long and
// cmnt instances!), processed as a second 2-row pass for s < 128 under the same barrier.
// whh sharded by h-column (rank owns 64 cols -> 192 gate-rows). 256 thr; per-thread
// 4 rows x 1 col x K/4, kq interleaved at 16B granularity (proven conflict-free R13
// layout). Butterfly shfl leaves full sums in all lanes; lane kq owns long row kq,
// lanes kq<2 own cmnt row kq. Split cluster barrier hides gi prefetch + peer skew.
// smem: Ws[192][260] + Hs[2][4][260] + Hc[2][2][260] = 212160 B dynamic.
__global__ __launch_bounds__(256) __cluster_dims__(4, 1, 1) void k_scan_cl(
    const float* __restrict__ whhf, const float* __restrict__ whhb,
    const float* __restrict__ bhhf, const float* __restrict__ bhhb,
    const float* __restrict__ w2)
{
    extern __shared__ float sm[];
    float* Ws  = sm;                  // [(g*64+cc)*260 + k]
    float* Hs0 = sm + 192*260;        // long H: [4][260] x2
    float* Hs1 = Hs0 + 4*260;
    float* Hc0 = Hs1 + 4*260;         // cmnt H: [2][260] x2
    float* Hc1 = Hc0 + 2*260;

    const unsigned rank = cta_rank();
    const int cl   = blockIdx.x >> 2;
    const int inst = cl >> 3;                   // long instance 0..3
    const int r0   = (cl & 7) * 4;              // 4 long batch rows
    const int dir  = inst & 1;
    const int rc0  = 2*((inst >> 1)*8 + (cl & 7));   // 2 carried cmnt rows (per dir)
    const int c0   = rank * 64;
    const float* whh = dir ? whhb : whhf;
    const float* bhh = dir ? bhhb : bhhf;
    const float* gi_base  = &g_gi[inst][0];
    const float* gic_base = &g_gic[dir][0];
    float* out_base = &g_ctx[inst>>1][0];

    const int tid  = threadIdx.x;
    const int w    = tid >> 5;
    const int lane = tid & 31;
    const int kq   = lane >> 3;          // K quarter (shfl-reducible: xor 8,16)
    const int cs   = lane & 7;
    const int c    = c0 + w*8 + cs;      // global h-col 0..255
    const int koff = kq * 4;             // 16B-interleaved k offset (floats)

    // load whh shard: 192 rows (3 gates x 64 cols) x 256
    for (int q = tid; q < 192*64; q += 256) {
        int row = q >> 6, kk = (q & 63) * 4;
        int g = row >> 6, cc = row & 63;
        *(float4*)&Ws[row*260 + kk] =
            *(const float4*)(whh + (size_t)(g*256 + c0 + cc)*Dz + kk);
    }
    // zero all H buffers (h0 = 0): 2*4*260 long + 2*2*260 cmnt = 3120 floats
    for (int q = tid; q < 12*260; q += 256) Hs0[q] = 0.f;

    const float bR = bhh[c], bZ = bhh[256+c], bN = bhh[512+c];
    const float w2c = w2[dir*256 + c];
    const int cw = w*8 + cs;
    const float* wr = &Ws[(0*64 + cw)*260 + koff];
    const float* wz = &Ws[(1*64 + cw)*260 + koff];
    const float* wn = &Ws[(2*64 + cw)*260 + koff];
    const unsigned hn_u32[2]  = { smem_u32(Hs0), smem_u32(Hs1) };
    const unsigned hcn_u32[2] = { smem_u32(Hc0), smem_u32(Hc1) };

    __syncthreads();
    CLUSTER_ARRIVE();    // release zeroed buffers

    for (int s = 0; s < Tz; s++) {
        const float* Hb  = (s & 1) ? Hs1 : Hs0;
        const float* Hc  = Hb + koff;
        const float* Hcb = (s & 1) ? Hc1 : Hc0;
        const unsigned HnU  = hn_u32[(s & 1) ^ 1];
        const unsigned HcnU = hcn_u32[(s & 1) ^ 1];
        const bool cm_on = (s < Jz);

        // prefetch gi for this lane's epilogue rows (issued before the barrier wait)
        float gr, gz, gn;          // long row kq
        float cr = 0.f, cz = 0.f, cn = 0.f;  // cmnt row kq (lanes kq<2)
        {
            const float* gp = gi_base + (size_t)(s*32 + r0 + kq)*Gz;
            gr = __ldcs(gp + c); gz = __ldcs(gp + 256 + c); gn = __ldcs(gp + 512 + c);
            if (cm_on && kq < 2) {
                const float* gq = gic_base + (size_t)(s*32 + rc0 + kq)*Gz;
                cr = __ldcs(gq + c); cz = __ldcs(gq + 256 + c); cn = __ldcs(gq + 512 + c);
            }
        }
        CLUSTER_WAIT();   // prev-step DSMEM stores now visible

        // ---- pass 1: long instance, 4 rows (proven R13 mainloop) ----
        unsigned long long aR[4], aZ[4], aN[4];
#pragma unroll
        for (int i = 0; i < 4; i++) { aR[i]=0ull; aZ[i]=0ull; aN[i]=0ull; }
#pragma unroll 4
        for (int q = 0; q < 16; q++) {
            const int off = q * 16;      // 16 floats per interleave group
            ulonglong2 vr = *(const ulonglong2*)(wr + off);
            ulonglong2 vz = *(const ulonglong2*)(wz + off);
            ulonglong2 vn = *(const ulonglong2*)(wn + off);
#pragma unroll
            for (int i = 0; i < 4; i++) {
                ulonglong2 x = *(const ulonglong2*)(Hc + i*260 + off);
                ffma2(aR[i], x.x, vr.x); ffma2(aR[i], x.y, vr.y);
                ffma2(aZ[i], x.x, vz.x); ffma2(aZ[i], x.y, vz.y);
                ffma2(aN[i], x.x, vn.x); ffma2(aN[i], x.y, vn.y);
            }
        }
        float sR[4], sZ[4], sN[4];
#pragma unroll
        for (int i = 0; i < 4; i++) {
            float2 u;
            u = unpk(aR[i]); sR[i] = u.x + u.y;
            u = unpk(aZ[i]); sZ[i] = u.x + u.y;
            u = unpk(aN[i]); sN[i] = u.x + u.y;
            sR[i] += __shfl_xor_sync(0xFFFFFFFFu, sR[i], 8);
            sR[i] += __shfl_xor_sync(0xFFFFFFFFu, sR[i], 16);
            sZ[i] += __shfl_xor_sync(0xFFFFFFFFu, sZ[i], 8);
            sZ[i] += __shfl_xor_sync(0xFFFFFFFFu, sZ[i], 16);
            sN[i] += __shfl_xor_sync(0xFFFFFFFFu, sN[i], 8);
            sN[i] += __shfl_xor_sync(0xFFFFFFFFu, sN[i], 16);
        }
        // long epilogue: lane kq owns local row kq
        {
            const int tact = dir ? (Tz - 1 - s) : s;
            float rr2 = fsig(gr + sR[kq] + bR);
            float zz  = fsig(gz + sZ[kq] + bZ);
            float nn  = ftanh(gn + rr2*(sN[kq] + bN));
            float hp  = Hb[kq*260 + c];
            float h   = (1.f - zz)*nn + zz*hp;
            out_base[((size_t)(r0+kq)*Tz + tact)*(2*Dz) + dir*256 + c] = h * w2c;
            unsigned a = HnU + (unsigned)(kq*260 + c) * 4u;
#pragma unroll
            for (unsigned p = 0; p < 4; p++) st_dsmem(a, p, h);
        }

        // ---- pass 2: carried cmnt rows (s < 128 only), 2 rows, same W shard ----
        if (cm_on) {
            unsigned long long bR2[2], bZ2[2], bN2[2];
#pragma unroll
            for (int i = 0; i < 2; i++) { bR2[i]=0ull; bZ2[i]=0ull; bN2[i]=0ull; }
#pragma unroll 4
            for (int q = 0; q < 16; q++) {
                const int off = q * 16;
                ulonglong2 vr = *(const ulonglong2*)(wr + off);
                ulonglong2 vz = *(const ulonglong2*)(wz + off);
                ulonglong2 vn = *(const ulonglong2*)(wn + off);
#pragma unroll
                for (int i = 0; i < 2; i++) {
                    ulonglong2 x = *(const ulonglong2*)(Hcb + i*260 + koff + off);
                    ffma2(bR2[i], x.x, vr.x); ffma2(bR2[i], x.y, vr.y);
                    ffma2(bZ2[i], x.x, vz.x); ffma2(bZ2[i], x.y, vz.y);
                    ffma2(bN2[i], x.x, vn.x); ffma2(bN2[i], x.y, vn.y);
                }
            }
            float tR[2], tZ[2], tN[2];
#pragma unroll
            for (int i = 0; i < 2; i++) {
                float2 u;
                u = unpk(bR2[i]); tR[i] = u.x + u.y;
                u = unpk(bZ2[i]); tZ[i] = u.x + u.y;
                u = unpk(bN2[i]); tN[i] = u.x + u.y;
                tR[i] += __shfl_xor_sync(0xFFFFFFFFu, tR[i], 8);
                tR[i] += __shfl_xor_sync(0xFFFFFFFFu, tR[i], 16);
                tZ[i] += __shfl_xor_sync(0xFFFFFFFFu, tZ[i], 8);
                tZ[i] += __shfl_xor_sync(0xFFFFFFFFu, tZ[i], 16);
                tN[i] += __shfl_xor_sync(0xFFFFFFFFu, tN[i], 8);
                tN[i] += __shfl_xor_sync(0xFFFFFFFFu, tN[i], 16);
            }
            if (kq < 2) {
                const int tact = dir ? (Jz - 1 - s) : s;
                float rr2 = fsig(cr + tR[kq] + bR);
                float zz  = fsig(cz + tZ[kq] + bZ);
                float nn  = ftanh(cn + rr2*(tN[kq] + bN));
                float hp  = Hcb[kq*260 + c];
                float h   = (1.f - zz)*nn + zz*hp;
                g_cm[((size_t)(rc0+kq)*Jz + tact)*(2*Dz) + dir*256 + c] = h;
                unsigned a = HcnU + (unsigned)(kq*260 + c) * 4u;
#pragma unroll
                for (unsigned p = 0; p < 4; p++) st_dsmem(a, p, h);
            }
        }
        CLUSTER_ARRIVE();   // release this step's DSMEM stores (both passes)
    }
    CLUSTER_WAIT();         // consume final arrive before exit
}

// ------------- S[b,t,j] = sum_d ctxS[b,t,d]*cm[b,j,d] + action*w2[512] (FFMA2) -------------
__global__ __launch_bounds__(256) void k_sim(
    const int* __restrict__ src_act, const int* __restrict__ tgt_act,
    const float* __restrict__ w2)
{
    const int side = blockIdx.z;
    const int b    = blockIdx.y;
    const int tb   = blockIdx.x * 64;
    const float* A = &g_ctx[side][(size_t)b*Tz*2*Dz];   // [t][512]
    const float* Bm= &g_cm[(size_t)b*Jz*2*Dz];          // [j][512]
    const int* act = side ? tgt_act : src_act;
    const float wA = w2[2*Dz];

    __shared__ float As[16][68];
    __shared__ float Bs[16][132];
    const int tid = threadIdx.x;
    const int tx = tid & 15, ty = tid >> 4;
    const int lrA = tid >> 2, lkA = (tid & 3) * 4;
    const int lrB = tid >> 1, lkB = (tid & 1) * 8;

    unsigned long long acc[4][4];   // [i][jpair]
#pragma unroll
    for (int i = 0; i < 4; i++)
#pragma unroll
        for (int q = 0; q < 4; q++) acc[i][q] = 0ull;

    const float* Arow = A + (size_t)(tb + lrA)*(2*Dz);
    const float* Brow = Bm + (size_t)lrB*(2*Dz);

    for (int k0 = 0; k0 < 2*Dz; k0 += 16) {
        float4 a = *(const float4*)(Arow + k0 + lkA);
        As[lkA+0][lrA]=a.x; As[lkA+1][lrA]=a.y; As[lkA+2][lrA]=a.z; As[lkA+3][lrA]=a.w;
        float4 b0 = *(const float4*)(Brow + k0 + lkB);
        float4 b1 = *(const float4*)(Brow + k0 + lkB + 4);
        Bs[lkB+0][lrB]=b0.x; Bs[lkB+1][lrB]=b0.y; Bs[lkB+2][lrB]=b0.z; Bs[lkB+3][lrB]=b0.w;
        Bs[lkB+4][lrB]=b1.x; Bs[lkB+5][lrB]=b1.y; Bs[lkB+6][lrB]=b1.z; Bs[lkB+7][lrB]=b1.w;
        __syncthreads();
#pragma unroll
        for (int kk = 0; kk < 16; kk++) {
            float4 ra = *(const float4*)&As[kk][ty*4];
            unsigned long long ad[4] = { dup2(ra.x), dup2(ra.y), dup2(ra.z), dup2(ra.w) };
            ulonglong2 b01 = *(const ulonglong2*)&Bs[kk][tx*8];
            ulonglong2 b23 = *(const ulonglong2*)&Bs[kk][tx*8+4];
            unsigned long long bp[4] = { b01.x, b01.y, b23.x, b23.y };
#pragma unroll
            for (int i = 0; i < 4; i++)
#pragma unroll
                for (int q = 0; q < 4; q++) ffma2(acc[i][q], ad[i], bp[q]);
        }
        __syncthreads();
    }
#pragma unroll
    for (int i = 0; i < 4; i++) {
        int t = tb + ty*4 + i;
        float aterm = (float)act[b*Tz + t] * wA;
        float* Sp = &g_S[side][((size_t)b*Tz + t)*Jz];
        float v[8];
#pragma unroll
        for (int q = 0; q < 4; q++) {
            float2 u = unpk(acc[i][q]);
            v[2*q] = u.x + aterm; v[2*q+1] = u.y + aterm;
        }
        *(float4*)&Sp[tx*8]   = *(float4*)&v[0];
        *(float4*)&Sp[tx*8+4] = *(float4*)&v[4];
    }
}

// --------- per (side,b): m_t = max_j S; w = softmax_t(m); out_j = sum_t w_t S[t,j] ---------
__global__ __launch_bounds__(256) void k_reduce() {
    const int b = blockIdx.x, side = blockIdx.y;
    const float* S = &g_S[side][(size_t)b*Tz*Jz];
    __shared__ float mrow[512];
    __shared__ float red[256];
    const int tid = threadIdx.x;

    for (int t = tid; t < Tz; t += 256) {
        const float4* row = (const float4*)(S + (size_t)t*Jz);
        float m = -3.4e38f;
#pragma unroll 4
        for (int q = 0; q < 32; q++) {
            float4 v = row[q];
            m = fmaxf(m, fmaxf(fmaxf(v.x, v.y), fmaxf(v.z, v.w)));
        }
        mrow[t] = m;
    }
    __syncthreads();
    red[tid] = fmaxf(mrow[tid], mrow[tid+256]);
    __syncthreads();
    for (int st = 128; st > 0; st >>= 1) {
        if (tid < st) red[tid] = fmaxf(red[tid], red[tid+st]);
        __syncthreads();
    }
    float M = red[0];
    __syncthreads();
    float e1 = __expf(mrow[tid] - M), e2 = __expf(mrow[tid+256] - M);
    mrow[tid] = e1; mrow[tid+256] = e2;
    red[tid] = e1 + e2;
    __syncthreads();
    for (int st = 128; st > 0; st >>= 1) {
        if (tid < st) red[tid] += red[tid+st];
        __syncthreads();
    }
    float inv = 1.f / red[0];
    __syncthreads();
    mrow[tid] *= inv; mrow[tid+256] *= inv;
    __syncthreads();

    const int j = tid & 127, half = tid >> 7;
    float acc = 0.f;
    for (int t = half*256; t < half*256 + 256; t++)
        acc += mrow[t] * S[(size_t)t*Jz + j];
    red[tid] = acc;
    __syncthreads();
    if (tid < 128)
        g_Sd[b*(2*Jz) + side*Jz + j] = red[j] + red[128 + j];
}

// ---------------- result = S_diff @ rank_w + rank_b; emit (result, S_diff) ----------------
__global__ __launch_bounds__(256) void k_final(
    const float* __restrict__ rank_w, const float* __restrict__ rank_b,
    float* __restrict__ out)
{
    const int tid = threadIdx.x;
    for (int i = tid; i < Bz*2*Jz; i += 256) out[32 + i] = g_Sd[i];
    __shared__ float red[256];
    const int b = tid >> 3, l = tid & 7;
    float p = 0.f;
    for (int q = l; q < 2*Jz; q += 8) p += g_Sd[b*(2*Jz) + q] * rank_w[q];
    red[tid] = p;
    __syncthreads();
    if (l == 0) {
        float s = 0.f;
#pragma unroll
        for (int k = 0; k < 8; k++) s += red[b*8 + k];
        out[b] = s + rank_b[0];
    }
}

// ------------------------- launch -------------------------
extern "C" void kernel_launch(void* const* d_in, const int* in_sizes, int n_in,
                              void* d_out, int out_size) {
    const int*   cm_tok = (const int*)  d_in[0];
    const int*   src_t  = (const int*)  d_in[1];
    const int*   tgt_t  = (const int*)  d_in[2];
    const int*   src_a  = (const int*)  d_in[3];
    const int*   tgt_a  = (const int*)  d_in[4];
    const float* emb    = (const float*)d_in[5];
    const float* wihf   = (const float*)d_in[6];
    const float* whhf   = (const float*)d_in[7];
    const float* bihf   = (const float*)d_in[8];
    const float* bhhf   = (const float*)d_in[9];
    const float* wihb   = (const float*)d_in[10];
    const float* whhb   = (const float*)d_in[11];
    const float* bihb   = (const float*)d_in[12];
    const float* bhhb   = (const float*)d_in[13];
    const float* w2     = (const float*)d_in[14];
    const float* rank_w = (const float*)d_in[15];
    const float* rank_b = (const float*)d_in[16];
    float* out = (float*)d_out;

    const int scanSmem = (192*260 + 2*4*260 + 2*2*260) * sizeof(float);  // 212160 B
    cudaFuncSetAttribute(k_scan_cl, cudaFuncAttributeMaxDynamicSharedMemorySize, scanSmem);

    k_gi<<<dim3(128, 12, 6), 256>>>(cm_tok, src_t, tgt_t, emb, wihf, bihf, wihb, bihb);
    // 32 clusters x 4 CTAs = 128 CTAs; cmnt rows carried inside (shared weights)
    k_scan_cl<<<128, 256, scanSmem>>>(whhf, whhb, bhhf, bhhb, w2);
    k_sim<<<dim3(8, 32, 2), 256>>>(src_a, tgt_a, w2);
    k_reduce<<<dim3(32, 2), 256>>>();
    k_final<<<1, 256>>>(rank_w, rank_b, out);
}